// round 6
// baseline (speedup 1.0000x reference)
#include <cuda_runtime.h>
#include <cstdint>

#define NMAX   100000
#define EMAX   1600000
#define NFEAT  256
#define NHID   64
#define NEG_SLOPE 0.2f
#define SCAN_BLK 1024
#define MAX_BLKS 128

// ---------------- scratch ----------------------------------------------------
__device__ float              g_xp[(size_t)NMAX * NHID];   // 25.6MB
__device__ float              g_ssrc[NMAX];
__device__ float              g_sdst[NMAX];
__device__ int                g_deg[NMAX];
__device__ int                g_rowptr[NMAX + 1];
__device__ int                g_wpos[NMAX];
__device__ int                g_bsum[MAX_BLKS];
__device__ int                g_boff[MAX_BLKS];
__device__ unsigned long long g_edge[EMAX + NMAX];         // packed (src, ex)
__device__ int                g_is64;

// ---------------- detect dtype + zero deg ------------------------------------
__global__ void detect_kernel(const unsigned int* __restrict__ w, int Nn) {
    int idx = blockIdx.x * blockDim.x + threadIdx.x;
    if (idx < Nn) g_deg[idx] = 0;
    if (blockIdx.x == 0) {
        __shared__ int any;
        if (threadIdx.x == 0) any = 0;
        __syncthreads();
        int found = 0;
        for (int i = 1 + 2 * threadIdx.x; i < 4096; i += 2 * blockDim.x)
            if (w[i] != 0u) found = 1;
        if (found) atomicExch(&any, 1);
        __syncthreads();
        if (threadIdx.x == 0) g_is64 = (any == 0) ? 1 : 0;
    }
}

__device__ __forceinline__ void load_edge(const void* ei, int i, int E,
                                          int is64, int& s, int& d) {
    if (i < E) {
        if (is64) {
            const long long* p = (const long long*)ei;
            s = (int)p[i]; d = (int)p[E + i];
        } else {
            const int* p = (const int*)ei;
            s = p[i]; d = p[E + i];
        }
    } else {
        s = d = i - E;
    }
}

// ---------------- GEMM + fused s-vectors: 128-row tile, 8x4 thread tile ------
#define XPAD 260
#define WPAD 258
__global__ void __launch_bounds__(256, 1)
gemm_kernel(const float* __restrict__ x, const float* __restrict__ W,
            const float* __restrict__ a_src, const float* __restrict__ a_dst,
            int Nn) {
    extern __shared__ float sm[];
    float* Wt = sm;                      // [64][WPAD]
    float* xs = sm + 64 * WPAD;          // [128][XPAD]
    const int tid  = threadIdx.x;
    const int row0 = blockIdx.x * 128;

    for (int i = tid; i < NFEAT * NHID; i += 256) {
        int k = i >> 6, c = i & 63;
        Wt[c * WPAD + k] = W[i];
    }
    for (int i = tid; i < 128 * (NFEAT / 4); i += 256) {
        int r  = i / (NFEAT / 4);
        int k4 = i % (NFEAT / 4);
        float4 v = make_float4(0.f, 0.f, 0.f, 0.f);
        int row = row0 + r;
        if (row < Nn)
            v = ((const float4*)(x + (size_t)row * NFEAT))[k4];
        *(float4*)(xs + r * XPAD + k4 * 4) = v;
    }
    __syncthreads();

    const int tx = tid & 15, ty = tid >> 4;
    const int r0 = ty * 8;
    unsigned long long acc[8][4];
    #pragma unroll
    for (int r = 0; r < 8; r++)
        #pragma unroll
        for (int c = 0; c < 4; c++) acc[r][c] = 0ull;

    #pragma unroll 2
    for (int k = 0; k < NFEAT; k += 2) {
        unsigned long long av[8], bv[4];
        #pragma unroll
        for (int c = 0; c < 4; c++)
            bv[c] = *(const unsigned long long*)(Wt + (tx + 16 * c) * WPAD + k);
        #pragma unroll
        for (int r = 0; r < 8; r++)
            av[r] = *(const unsigned long long*)(xs + (r0 + r) * XPAD + k);
        #pragma unroll
        for (int r = 0; r < 8; r++)
            #pragma unroll
            for (int c = 0; c < 4; c++)
                asm("fma.rn.f32x2 %0, %1, %2, %0;"
                    : "+l"(acc[r][c]) : "l"(av[r]), "l"(bv[c]));
    }

    float as[4], ad[4];
    #pragma unroll
    for (int c = 0; c < 4; c++) {
        as[c] = a_src[tx + 16 * c];
        ad[c] = a_dst[tx + 16 * c];
    }
    #pragma unroll
    for (int r = 0; r < 8; r++) {
        int row = row0 + r0 + r;
        float val[4];
        #pragma unroll
        for (int c = 0; c < 4; c++) {
            float2 p = *(float2*)&acc[r][c];
            val[c] = p.x + p.y;
        }
        float ps = val[0] * as[0] + val[1] * as[1] + val[2] * as[2] + val[3] * as[3];
        float pd = val[0] * ad[0] + val[1] * ad[1] + val[2] * ad[2] + val[3] * ad[3];
        #pragma unroll
        for (int o = 8; o > 0; o >>= 1) {
            ps += __shfl_down_sync(0xffffffffu, ps, o, 16);
            pd += __shfl_down_sync(0xffffffffu, pd, o, 16);
        }
        if (row < Nn) {
            #pragma unroll
            for (int c = 0; c < 4; c++)
                g_xp[(size_t)row * NHID + tx + 16 * c] = val[c];
            if (tx == 0) { g_ssrc[row] = ps; g_sdst[row] = pd; }
        }
    }
}

// ---------------- CSR: histogram (dst only) -----------------------------------
__global__ void hist_kernel(const void* __restrict__ ei, int E, int Nn) {
    int i = blockIdx.x * blockDim.x + threadIdx.x;
    if (i >= E + Nn) return;
    int d;
    if (i < E)
        d = g_is64 ? (int)((const long long*)ei)[E + i] : ((const int*)ei)[E + i];
    else
        d = i - E;
    atomicAdd(&g_deg[d], 1);
}

// ---------------- CSR: 3-phase scan --------------------------------------------
__global__ void scan1_kernel(int Nn) {
    __shared__ int warp_sums[32];
    const int lane = threadIdx.x & 31, wid = threadIdx.x >> 5;
    int idx = blockIdx.x * SCAN_BLK + threadIdx.x;
    int v = (idx < Nn) ? g_deg[idx] : 0;
    int xv = v;
    #pragma unroll
    for (int o = 1; o < 32; o <<= 1) {
        int y = __shfl_up_sync(0xffffffffu, xv, o);
        if (lane >= o) xv += y;
    }
    if (lane == 31) warp_sums[wid] = xv;
    __syncthreads();
    if (wid == 0) {
        int w = warp_sums[lane];
        #pragma unroll
        for (int o = 1; o < 32; o <<= 1) {
            int y = __shfl_up_sync(0xffffffffu, w, o);
            if (lane >= o) w += y;
        }
        warp_sums[lane] = w;
    }
    __syncthreads();
    int prefix = wid ? warp_sums[wid - 1] : 0;
    if (idx < Nn) g_rowptr[idx] = prefix + xv - v;
    if (threadIdx.x == SCAN_BLK - 1) g_bsum[blockIdx.x] = warp_sums[31];
}

__global__ void scan2_kernel(int nblk, int Nn) {
    __shared__ int warp_sums[4];
    const int lane = threadIdx.x & 31, wid = threadIdx.x >> 5;
    int v = (threadIdx.x < nblk) ? g_bsum[threadIdx.x] : 0;
    int xv = v;
    #pragma unroll
    for (int o = 1; o < 32; o <<= 1) {
        int y = __shfl_up_sync(0xffffffffu, xv, o);
        if (lane >= o) xv += y;
    }
    if (lane == 31) warp_sums[wid] = xv;
    __syncthreads();
    int pre = 0;
    for (int w = 0; w < wid; w++) pre += warp_sums[w];
    if (threadIdx.x < nblk) g_boff[threadIdx.x] = pre + xv - v;
    if (threadIdx.x == 127) g_rowptr[Nn] = pre + xv;
}

__global__ void scan3_kernel(int Nn) {
    int idx = blockIdx.x * SCAN_BLK + threadIdx.x;
    if (idx >= Nn) return;
    int r = g_rowptr[idx] + g_boff[blockIdx.x];
    g_rowptr[idx] = r;
    g_wpos[idx]   = r;
}

// ---------------- placement + per-edge exp (after gemm join) -------------------
// thread-per-edge, throughput-bound: edge load, 2 random s-gathers, exp,
// atomic slot claim, 8B record scatter. Shift-free softmax (logits ~|4|).
__global__ void place_ex_kernel(const void* __restrict__ ei, int E, int Nn) {
    int i = blockIdx.x * blockDim.x + threadIdx.x;
    if (i >= E + Nn) return;
    int s, d;
    load_edge(ei, i, E, g_is64, s, d);
    float e = __ldg(&g_ssrc[s]) + __ldg(&g_sdst[d]);
    e = e > 0.f ? e : NEG_SLOPE * e;
    float ex = __expf(e);
    int pos = atomicAdd(&g_wpos[d], 1);
    g_edge[pos] = (unsigned long long)(unsigned int)s |
                  ((unsigned long long)__float_as_uint(ex) << 32);
}

// ---------------- aggregate: warp/node, 2-level chain, batch-8 MLP -------------
__global__ void __launch_bounds__(256)
aggregate_kernel(const float* __restrict__ bias, float* __restrict__ out, int Nn) {
    int n    = (blockIdx.x * blockDim.x + threadIdx.x) >> 5;
    int lane = threadIdx.x & 31;
    if (n >= Nn) return;
    int beg = g_rowptr[n], end = g_rowptr[n + 1];
    float ax = 0.f, ay = 0.f, denom = 0.f;

    int j = beg;
    for (; j + 8 <= end; j += 8) {
        unsigned long long r[8];
        float2 v[8];
        #pragma unroll
        for (int t = 0; t < 8; t++) r[t] = __ldg(&g_edge[j + t]);  // uniform
        #pragma unroll
        for (int t = 0; t < 8; t++)
            v[t] = __ldg((const float2*)(g_xp +
                        (size_t)(unsigned int)r[t] * NHID + 2 * lane));
        #pragma unroll
        for (int t = 0; t < 8; t++) {
            float ex = __uint_as_float((unsigned int)(r[t] >> 32));
            denom += ex;
            ax += ex * v[t].x;
            ay += ex * v[t].y;
        }
    }
    for (; j < end; j++) {
        unsigned long long r0 = __ldg(&g_edge[j]);
        float ex = __uint_as_float((unsigned int)(r0 >> 32));
        float2 v0 = __ldg((const float2*)(g_xp +
                        (size_t)(unsigned int)r0 * NHID + 2 * lane));
        denom += ex;
        ax += ex * v0.x; ay += ex * v0.y;
    }
    float inv = 1.f / denom;
    float2 b = *(const float2*)(bias + 2 * lane);
    *(float2*)(out + (size_t)n * NHID + 2 * lane) =
        make_float2(ax * inv + b.x, ay * inv + b.y);
}

// ---------------- launch ---------------------------------------------------------
extern "C" void kernel_launch(void* const* d_in, const int* in_sizes, int n_in,
                              void* d_out, int out_size) {
    const float* x     = (const float*)d_in[0];
    const void*  ei    = d_in[1];
    const float* W     = (const float*)d_in[2];
    const float* a_src = (const float*)d_in[3];
    const float* a_dst = (const float*)d_in[4];
    const float* bias  = (const float*)d_in[5];
    float* out = (float*)d_out;

    const int Nn = in_sizes[0] / NFEAT;
    const int E  = in_sizes[1] / 2;
    const int T  = E + Nn;
    const int nblk = (Nn + SCAN_BLK - 1) / SCAN_BLK;

    const int smem = (64 * WPAD + 128 * XPAD) * (int)sizeof(float);
    cudaFuncSetAttribute(gemm_kernel,
                         cudaFuncAttributeMaxDynamicSharedMemorySize, smem);

    cudaStream_t s2;
    cudaEvent_t evFork, evJoin;
    cudaStreamCreateWithFlags(&s2, cudaStreamNonBlocking);
    cudaEventCreateWithFlags(&evFork, cudaEventDisableTiming);
    cudaEventCreateWithFlags(&evJoin, cudaEventDisableTiming);

    cudaEventRecord(evFork, 0);
    cudaStreamWaitEvent(s2, evFork, 0);

    // stream B: CSR structure (independent of features)
    detect_kernel<<<(Nn + 255) / 256, 256, 0, s2>>>((const unsigned int*)ei, Nn);
    hist_kernel<<<(T + 255) / 256, 256, 0, s2>>>(ei, E, Nn);
    scan1_kernel<<<nblk, SCAN_BLK, 0, s2>>>(Nn);
    scan2_kernel<<<1, 128, 0, s2>>>(nblk, Nn);
    scan3_kernel<<<nblk, SCAN_BLK, 0, s2>>>(Nn);
    cudaEventRecord(evJoin, s2);

    // stream A: GEMM + fused s-vectors
    gemm_kernel<<<(Nn + 127) / 128, 256, smem>>>(x, W, a_src, a_dst, Nn);

    // join, then edge exp+placement, then aggregate
    cudaStreamWaitEvent(0, evJoin, 0);
    place_ex_kernel<<<(T + 255) / 256, 256>>>(ei, E, Nn);
    aggregate_kernel<<<(Nn * 32 + 255) / 256, 256>>>(bias, out, Nn);
}

// round 7
// speedup vs baseline: 1.1035x; 1.1035x over previous
#include <cuda_runtime.h>
#include <cuda_fp16.h>
#include <cstdint>

#define NMAX   100000
#define EMAX   1600000
#define NFEAT  256
#define NHID   64
#define NEG_SLOPE 0.2f
#define SCAN_BLK 1024
#define MAX_BLKS 128

// ---------------- scratch ----------------------------------------------------
__device__ __half g_xph[(size_t)NMAX * NHID];   // fp16 features 12.8MB
__device__ float  g_ssrc[NMAX];
__device__ float  g_sdst[NMAX];
__device__ int    g_deg[NMAX];
__device__ int    g_rowptr[NMAX + 1];
__device__ int    g_wpos[NMAX];
__device__ int    g_bsum[MAX_BLKS];
__device__ int    g_boff[MAX_BLKS];
__device__ int    g_esrc[EMAX + NMAX];          // CSR src ids (by dst)
__device__ int    g_is64;

// ---------------- detect dtype + zero deg ------------------------------------
__global__ void detect_kernel(const unsigned int* __restrict__ w, int Nn) {
    int idx = blockIdx.x * blockDim.x + threadIdx.x;
    if (idx < Nn) g_deg[idx] = 0;
    if (blockIdx.x == 0) {
        __shared__ int any;
        if (threadIdx.x == 0) any = 0;
        __syncthreads();
        int found = 0;
        for (int i = 1 + 2 * threadIdx.x; i < 4096; i += 2 * blockDim.x)
            if (w[i] != 0u) found = 1;
        if (found) atomicExch(&any, 1);
        __syncthreads();
        if (threadIdx.x == 0) g_is64 = (any == 0) ? 1 : 0;
    }
}

__device__ __forceinline__ void load_edge(const void* ei, int i, int E,
                                          int is64, int& s, int& d) {
    if (i < E) {
        if (is64) {
            const long long* p = (const long long*)ei;
            s = (int)p[i]; d = (int)p[E + i];
        } else {
            const int* p = (const int*)ei;
            s = p[i]; d = p[E + i];
        }
    } else {
        s = d = i - E;
    }
}

// ---------------- GEMM + fused s-vectors, fp16 feature store ------------------
#define XPAD 260
#define WPAD 258
__global__ void __launch_bounds__(256, 1)
gemm_kernel(const float* __restrict__ x, const float* __restrict__ W,
            const float* __restrict__ a_src, const float* __restrict__ a_dst,
            int Nn) {
    extern __shared__ float sm[];
    float* Wt = sm;                      // [64][WPAD]
    float* xs = sm + 64 * WPAD;          // [128][XPAD]
    const int tid  = threadIdx.x;
    const int row0 = blockIdx.x * 128;

    for (int i = tid; i < NFEAT * NHID; i += 256) {
        int k = i >> 6, c = i & 63;
        Wt[c * WPAD + k] = W[i];
    }
    for (int i = tid; i < 128 * (NFEAT / 4); i += 256) {
        int r  = i / (NFEAT / 4);
        int k4 = i % (NFEAT / 4);
        float4 v = make_float4(0.f, 0.f, 0.f, 0.f);
        int row = row0 + r;
        if (row < Nn)
            v = ((const float4*)(x + (size_t)row * NFEAT))[k4];
        *(float4*)(xs + r * XPAD + k4 * 4) = v;
    }
    __syncthreads();

    const int tx = tid & 15, ty = tid >> 4;
    const int r0 = ty * 8;
    unsigned long long acc[8][4];
    #pragma unroll
    for (int r = 0; r < 8; r++)
        #pragma unroll
        for (int c = 0; c < 4; c++) acc[r][c] = 0ull;

    #pragma unroll 2
    for (int k = 0; k < NFEAT; k += 2) {
        unsigned long long av[8], bv[4];
        #pragma unroll
        for (int c = 0; c < 4; c++)
            bv[c] = *(const unsigned long long*)(Wt + (tx + 16 * c) * WPAD + k);
        #pragma unroll
        for (int r = 0; r < 8; r++)
            av[r] = *(const unsigned long long*)(xs + (r0 + r) * XPAD + k);
        #pragma unroll
        for (int r = 0; r < 8; r++)
            #pragma unroll
            for (int c = 0; c < 4; c++)
                asm("fma.rn.f32x2 %0, %1, %2, %0;"
                    : "+l"(acc[r][c]) : "l"(av[r]), "l"(bv[c]));
    }

    float as[4], ad[4];
    #pragma unroll
    for (int c = 0; c < 4; c++) {
        as[c] = a_src[tx + 16 * c];
        ad[c] = a_dst[tx + 16 * c];
    }
    #pragma unroll
    for (int r = 0; r < 8; r++) {
        int row = row0 + r0 + r;
        float val[4];
        #pragma unroll
        for (int c = 0; c < 4; c++) {
            float2 p = *(float2*)&acc[r][c];
            val[c] = p.x + p.y;
        }
        float ps = val[0] * as[0] + val[1] * as[1] + val[2] * as[2] + val[3] * as[3];
        float pd = val[0] * ad[0] + val[1] * ad[1] + val[2] * ad[2] + val[3] * ad[3];
        #pragma unroll
        for (int o = 8; o > 0; o >>= 1) {
            ps += __shfl_down_sync(0xffffffffu, ps, o, 16);
            pd += __shfl_down_sync(0xffffffffu, pd, o, 16);
        }
        if (row < Nn) {
            #pragma unroll
            for (int c = 0; c < 4; c++)
                g_xph[(size_t)row * NHID + tx + 16 * c] = __float2half(val[c]);
            if (tx == 0) { g_ssrc[row] = ps; g_sdst[row] = pd; }
        }
    }
}

// ---------------- CSR: histogram (dst only) -----------------------------------
__global__ void hist_kernel(const void* __restrict__ ei, int E, int Nn) {
    int i = blockIdx.x * blockDim.x + threadIdx.x;
    if (i >= E + Nn) return;
    int d;
    if (i < E)
        d = g_is64 ? (int)((const long long*)ei)[E + i] : ((const int*)ei)[E + i];
    else
        d = i - E;
    atomicAdd(&g_deg[d], 1);
}

// ---------------- CSR: 3-phase scan --------------------------------------------
__global__ void scan1_kernel(int Nn) {
    __shared__ int warp_sums[32];
    const int lane = threadIdx.x & 31, wid = threadIdx.x >> 5;
    int idx = blockIdx.x * SCAN_BLK + threadIdx.x;
    int v = (idx < Nn) ? g_deg[idx] : 0;
    int xv = v;
    #pragma unroll
    for (int o = 1; o < 32; o <<= 1) {
        int y = __shfl_up_sync(0xffffffffu, xv, o);
        if (lane >= o) xv += y;
    }
    if (lane == 31) warp_sums[wid] = xv;
    __syncthreads();
    if (wid == 0) {
        int w = warp_sums[lane];
        #pragma unroll
        for (int o = 1; o < 32; o <<= 1) {
            int y = __shfl_up_sync(0xffffffffu, w, o);
            if (lane >= o) w += y;
        }
        warp_sums[lane] = w;
    }
    __syncthreads();
    int prefix = wid ? warp_sums[wid - 1] : 0;
    if (idx < Nn) g_rowptr[idx] = prefix + xv - v;
    if (threadIdx.x == SCAN_BLK - 1) g_bsum[blockIdx.x] = warp_sums[31];
}

__global__ void scan2_kernel(int nblk, int Nn) {
    __shared__ int warp_sums[4];
    const int lane = threadIdx.x & 31, wid = threadIdx.x >> 5;
    int v = (threadIdx.x < nblk) ? g_bsum[threadIdx.x] : 0;
    int xv = v;
    #pragma unroll
    for (int o = 1; o < 32; o <<= 1) {
        int y = __shfl_up_sync(0xffffffffu, xv, o);
        if (lane >= o) xv += y;
    }
    if (lane == 31) warp_sums[wid] = xv;
    __syncthreads();
    int pre = 0;
    for (int w = 0; w < wid; w++) pre += warp_sums[w];
    if (threadIdx.x < nblk) g_boff[threadIdx.x] = pre + xv - v;
    if (threadIdx.x == 127) g_rowptr[Nn] = pre + xv;
}

__global__ void scan3_kernel(int Nn) {
    int idx = blockIdx.x * SCAN_BLK + threadIdx.x;
    if (idx >= Nn) return;
    int r = g_rowptr[idx] + g_boff[blockIdx.x];
    g_rowptr[idx] = r;
    g_wpos[idx]   = r;
}

// ---------------- CSR: placement (hidden stream, no gemm dependency) ----------
__global__ void place_kernel(const void* __restrict__ ei, int E, int Nn) {
    int i = blockIdx.x * blockDim.x + threadIdx.x;
    if (i >= E + Nn) return;
    int s, d;
    load_edge(ei, i, E, g_is64, s, d);
    int pos = atomicAdd(&g_wpos[d], 1);
    g_esrc[pos] = s;
}

// ---------------- aggregate: warp/node, 2 half-warp edge streams, fp16 rows ----
__global__ void __launch_bounds__(256)
aggregate_kernel(const float* __restrict__ bias, float* __restrict__ out, int Nn) {
    int n    = (blockIdx.x * blockDim.x + threadIdx.x) >> 5;
    int lane = threadIdx.x & 31;
    if (n >= Nn) return;
    const int half = lane >> 4;          // edge stream 0 or 1
    const int lh   = lane & 15;          // lane within half: cols 4*lh..4*lh+3

    int beg = g_rowptr[n], end = g_rowptr[n + 1];
    int len = end - beg;
    int mid = beg + ((len + 1) >> 1);
    int j    = half ? mid : beg;
    int jend = half ? end : mid;

    float sdn = g_sdst[n];
    float a0 = 0.f, a1 = 0.f, a2 = 0.f, a3 = 0.f, denom = 0.f;

    for (; j + 4 <= jend; j += 4) {
        int   sv[4];
        float ev[4];
        uint2 hv[4];
        #pragma unroll
        for (int t = 0; t < 4; t++) sv[t] = __ldg(&g_esrc[j + t]);
        #pragma unroll
        for (int t = 0; t < 4; t++) ev[t] = __ldg(&g_ssrc[sv[t]]);
        #pragma unroll
        for (int t = 0; t < 4; t++)
            hv[t] = __ldg((const uint2*)(g_xph + (size_t)sv[t] * NHID + 4 * lh));
        #pragma unroll
        for (int t = 0; t < 4; t++) {
            float e = ev[t] + sdn;
            e = e > 0.f ? e : NEG_SLOPE * e;
            float ex = __expf(e);
            denom += ex;
            float2 fa = __half22float2(*(const __half2*)&hv[t].x);
            float2 fb = __half22float2(*(const __half2*)&hv[t].y);
            a0 += ex * fa.x; a1 += ex * fa.y;
            a2 += ex * fb.x; a3 += ex * fb.y;
        }
    }
    for (; j < jend; j++) {
        int s0 = __ldg(&g_esrc[j]);
        float e = __ldg(&g_ssrc[s0]) + sdn;
        e = e > 0.f ? e : NEG_SLOPE * e;
        float ex = __expf(e);
        denom += ex;
        uint2 h0 = __ldg((const uint2*)(g_xph + (size_t)s0 * NHID + 4 * lh));
        float2 fa = __half22float2(*(const __half2*)&h0.x);
        float2 fb = __half22float2(*(const __half2*)&h0.y);
        a0 += ex * fa.x; a1 += ex * fa.y;
        a2 += ex * fb.x; a3 += ex * fb.y;
    }

    // combine the two half-warp streams (col layout identical across halves)
    denom += __shfl_xor_sync(0xffffffffu, denom, 16);
    a0 += __shfl_xor_sync(0xffffffffu, a0, 16);
    a1 += __shfl_xor_sync(0xffffffffu, a1, 16);
    a2 += __shfl_xor_sync(0xffffffffu, a2, 16);
    a3 += __shfl_xor_sync(0xffffffffu, a3, 16);

    if (half == 0) {
        float inv = 1.f / denom;
        float4 b = *(const float4*)(bias + 4 * lh);
        float4 o4 = make_float4(a0 * inv + b.x, a1 * inv + b.y,
                                a2 * inv + b.z, a3 * inv + b.w);
        *(float4*)(out + (size_t)n * NHID + 4 * lh) = o4;
    }
}

// ---------------- launch ---------------------------------------------------------
extern "C" void kernel_launch(void* const* d_in, const int* in_sizes, int n_in,
                              void* d_out, int out_size) {
    const float* x     = (const float*)d_in[0];
    const void*  ei    = d_in[1];
    const float* W     = (const float*)d_in[2];
    const float* a_src = (const float*)d_in[3];
    const float* a_dst = (const float*)d_in[4];
    const float* bias  = (const float*)d_in[5];
    float* out = (float*)d_out;

    const int Nn = in_sizes[0] / NFEAT;
    const int E  = in_sizes[1] / 2;
    const int T  = E + Nn;
    const int nblk = (Nn + SCAN_BLK - 1) / SCAN_BLK;

    const int smem = (64 * WPAD + 128 * XPAD) * (int)sizeof(float);
    cudaFuncSetAttribute(gemm_kernel,
                         cudaFuncAttributeMaxDynamicSharedMemorySize, smem);

    cudaStream_t s2;
    cudaEvent_t evFork, evJoin;
    cudaStreamCreateWithFlags(&s2, cudaStreamNonBlocking);
    cudaEventCreateWithFlags(&evFork, cudaEventDisableTiming);
    cudaEventCreateWithFlags(&evJoin, cudaEventDisableTiming);

    cudaEventRecord(evFork, 0);
    cudaStreamWaitEvent(s2, evFork, 0);

    // stream B: CSR structure + placement (independent of features)
    detect_kernel<<<(Nn + 255) / 256, 256, 0, s2>>>((const unsigned int*)ei, Nn);
    hist_kernel<<<(T + 255) / 256, 256, 0, s2>>>(ei, E, Nn);
    scan1_kernel<<<nblk, SCAN_BLK, 0, s2>>>(Nn);
    scan2_kernel<<<1, 128, 0, s2>>>(nblk, Nn);
    scan3_kernel<<<nblk, SCAN_BLK, 0, s2>>>(Nn);
    place_kernel<<<(T + 255) / 256, 256, 0, s2>>>(ei, E, Nn);
    cudaEventRecord(evJoin, s2);

    // stream A: GEMM + fused s-vectors + fp16 feature store
    gemm_kernel<<<(Nn + 127) / 128, 256, smem>>>(x, W, a_src, a_dst, Nn);

    cudaStreamWaitEvent(0, evJoin, 0);
    aggregate_kernel<<<(Nn * 32 + 255) / 256, 256>>>(bias, out, Nn);
}